// round 1
// baseline (speedup 1.0000x reference)
#include <cuda_runtime.h>
#include <math.h>

// ChamferReward: achieved/desired (128,4,1024,10) f32, mean/std (10) f32 -> out (128,1) f32.
// Masks in the reference are identically False, so the computation reduces to a
// bidirectional chamfer match on dims [5:9] with XY (dims [0:2]) partner distances.
//
// Grid: 1024 CTAs = 512 (b,v) slices x 2 directions.
//   pass 0 (g2s): owned = goals (desired), streamed = states (achieved)
//   pass 1 (s2g): owned = states (achieved), streamed = goals (desired)
// Each CTA writes sum(xy_dist) for its direction to g_partials[c];
// a tiny reduce kernel combines 8 partials per batch element:
//   out[b] = -(sum of 8 partials) / (1024 * 8)

#define N_PART 1024
#define THREADS 256
#define ITEMS 4

__device__ float g_partials[1024];

__global__ void __launch_bounds__(THREADS)
chamfer_pass_kernel(const float* __restrict__ achieved,
                    const float* __restrict__ desired,
                    const float* __restrict__ norm_mean,
                    const float* __restrict__ norm_std)
{
    __shared__ float4 svis[N_PART];   // streamed vis (normalized), 16KB
    __shared__ float  sbb[N_PART];    // streamed |vis|^2, 4KB
    __shared__ float2 sxy[N_PART];    // streamed xy (normalized), 8KB
    __shared__ float  warp_sums[THREADS / 32];

    const int c    = blockIdx.x;
    const int pass = c & 1;
    const int bv   = c >> 1;          // 0..511  (b*4 + v)

    const float* ownp;
    const float* strp;
    if (pass == 0) { ownp = desired;  strp = achieved; }
    else           { ownp = achieved; strp = desired;  }
    const size_t base = (size_t)bv * (size_t)N_PART * 10;
    ownp += base;
    strp += base;

    // Normalization constants (broadcast, cached)
    const float m0 = __ldg(norm_mean + 0), m1 = __ldg(norm_mean + 1);
    const float m5 = __ldg(norm_mean + 5), m6 = __ldg(norm_mean + 6);
    const float m7 = __ldg(norm_mean + 7), m8 = __ldg(norm_mean + 8);
    const float s0 = __ldg(norm_std  + 0), s1 = __ldg(norm_std  + 1);
    const float s5 = __ldg(norm_std  + 5), s6 = __ldg(norm_std  + 6);
    const float s7 = __ldg(norm_std  + 7), s8 = __ldg(norm_std  + 8);

    const int tid = threadIdx.x;

    // ---- Stage streamed side into smem (normalize + precompute |vis|^2) ----
    for (int i = tid; i < N_PART; i += THREADS) {
        const float* r = strp + i * 10;
        float x0 = fmaf(r[0], s0, m0);
        float x1 = fmaf(r[1], s1, m1);
        float v0 = fmaf(r[5], s5, m5);
        float v1 = fmaf(r[6], s6, m6);
        float v2 = fmaf(r[7], s7, m7);
        float v3 = fmaf(r[8], s8, m8);
        svis[i] = make_float4(v0, v1, v2, v3);
        sbb[i]  = v0 * v0 + v1 * v1 + v2 * v2 + v3 * v3;
        sxy[i]  = make_float2(x0, x1);
    }

    // ---- Owned items: register resident ----
    float a0[ITEMS], a1[ITEMS], a2[ITEMS], a3[ITEMS], aa[ITEMS];
    float ox[ITEMS], oy[ITEMS];
#pragma unroll
    for (int k = 0; k < ITEMS; k++) {
        const int i = tid + k * THREADS;
        const float* r = ownp + i * 10;
        ox[k] = fmaf(r[0], s0, m0);
        oy[k] = fmaf(r[1], s1, m1);
        a0[k] = fmaf(r[5], s5, m5);
        a1[k] = fmaf(r[6], s6, m6);
        a2[k] = fmaf(r[7], s7, m7);
        a3[k] = fmaf(r[8], s8, m8);
        aa[k] = a0[k] * a0[k] + a1[k] * a1[k] + a2[k] * a2[k] + a3[k] * a3[k];
    }

    __syncthreads();

    // ---- Main loop: min + argmin over streamed side for each owned item ----
    float bestd[ITEMS];
    int   bestj[ITEMS];
#pragma unroll
    for (int k = 0; k < ITEMS; k++) { bestd[k] = 3.4e38f; bestj[k] = 0; }

#pragma unroll 4
    for (int j = 0; j < N_PART; j++) {
        const float4 b  = svis[j];   // all-lane broadcast LDS.128
        const float  bb = sbb[j];    // broadcast LDS.32
#pragma unroll
        for (int k = 0; k < ITEMS; k++) {
            float dot = a0[k] * b.x + a1[k] * b.y + a2[k] * b.z + a3[k] * b.w;
            float d   = fmaf(dot, -2.0f, aa[k] + bb);
            // strict < keeps the FIRST minimum (matches jnp.argmin tie-break)
            if (d < bestd[k]) { bestd[k] = d; bestj[k] = j; }
        }
    }

    // ---- Tail: partner XY distance, threshold, accumulate ----
    float partial = 0.0f;
#pragma unroll
    for (int k = 0; k < ITEMS; k++) {
        const float2 p = sxy[bestj[k]];
        const float dx = ox[k] - p.x;
        const float dy = oy[k] - p.y;
        float xd = sqrtf(dx * dx + dy * dy);
        if (bestd[k] > 6.0f) xd = 1.0f;   // LATENT_DIST_THRESHOLD on squared dist
        partial += xd;
    }

    // ---- Block reduce (deterministic, no atomics) ----
#pragma unroll
    for (int off = 16; off > 0; off >>= 1)
        partial += __shfl_down_sync(0xffffffffu, partial, off);
    if ((tid & 31) == 0) warp_sums[tid >> 5] = partial;
    __syncthreads();
    if (tid == 0) {
        float s = 0.0f;
#pragma unroll
        for (int w = 0; w < THREADS / 32; w++) s += warp_sums[w];
        g_partials[c] = s;
    }
}

__global__ void chamfer_reduce_kernel(float* __restrict__ out)
{
    const int b = threadIdx.x;   // 128 threads
    float s = 0.0f;
#pragma unroll
    for (int t = 0; t < 8; t++) s += g_partials[b * 8 + t];
    out[b] = -s * (1.0f / (1024.0f * 8.0f));
}

extern "C" void kernel_launch(void* const* d_in, const int* in_sizes, int n_in,
                              void* d_out, int out_size)
{
    const float* achieved  = (const float*)d_in[0];
    const float* desired   = (const float*)d_in[1];
    const float* norm_mean = (const float*)d_in[2];
    const float* norm_std  = (const float*)d_in[3];
    float* out = (float*)d_out;

    chamfer_pass_kernel<<<1024, THREADS>>>(achieved, desired, norm_mean, norm_std);
    chamfer_reduce_kernel<<<1, 128>>>(out);
}

// round 2
// speedup vs baseline: 1.3889x; 1.3889x over previous
#include <cuda_runtime.h>
#include <math.h>

// ChamferReward — R2: packed f32x2 FMA inner loop.
//
// d'(k,j) = bb_j - 2*a_k·b_j  (aa_k dropped from the scan key; added back at the
// end for the threshold test). -2 folded into a'_k = -2*a_k (loop-invariant).
// Two consecutive j's are processed per packed fma.rn.f32x2; B-side is stored in
// shared memory component-major so packed operands load directly (LDS.64),
// A-side components are duplicated into both halves once, outside the loop.
//
// Grid: 1024 CTAs = 512 (b,v) slices x 2 directions. Partials -> tiny reduce.

#define N_PART 1024
#define NJP    512
#define THREADS 256
#define ITEMS   4

typedef unsigned long long ull;

__device__ float g_partials[1024];

#define FMA2(d, a, b, c) \
    asm("fma.rn.f32x2 %0, %1, %2, %3;" : "=l"(d) : "l"(a), "l"(b), "l"(c))

__device__ __forceinline__ ull pack_dup(float x) {
    ull r;
    unsigned xi = __float_as_uint(x);
    asm("mov.b64 %0, {%1, %1};" : "=l"(r) : "r"(xi));
    return r;
}

__device__ __forceinline__ void unpack2(ull v, float& lo, float& hi) {
    unsigned a, b;
    asm("mov.b64 {%0, %1}, %2;" : "=r"(a), "=r"(b) : "l"(v));
    lo = __uint_as_float(a);
    hi = __uint_as_float(b);
}

__global__ void __launch_bounds__(THREADS)
chamfer_pass_kernel(const float* __restrict__ achieved,
                    const float* __restrict__ desired,
                    const float* __restrict__ norm_mean,
                    const float* __restrict__ norm_std)
{
    // B-side, component-major over j-pairs: element jp packs (val_j, val_j+1).
    __shared__ ull sb0[NJP], sb1[NJP], sb2[NJP], sb3[NJP], sbb[NJP]; // 20KB
    __shared__ float2 sxy[N_PART];                                    // 8KB
    __shared__ float warp_sums[THREADS / 32];

    const int c    = blockIdx.x;
    const int pass = c & 1;
    const int bv   = c >> 1;

    const float* ownp;
    const float* strp;
    if (pass == 0) { ownp = desired;  strp = achieved; }
    else           { ownp = achieved; strp = desired;  }
    const size_t base = (size_t)bv * (size_t)N_PART * 10;
    ownp += base;
    strp += base;

    const float m0 = __ldg(norm_mean + 0), m1 = __ldg(norm_mean + 1);
    const float m5 = __ldg(norm_mean + 5), m6 = __ldg(norm_mean + 6);
    const float m7 = __ldg(norm_mean + 7), m8 = __ldg(norm_mean + 8);
    const float s0 = __ldg(norm_std  + 0), s1 = __ldg(norm_std  + 1);
    const float s5 = __ldg(norm_std  + 5), s6 = __ldg(norm_std  + 6);
    const float s7 = __ldg(norm_std  + 7), s8 = __ldg(norm_std  + 8);

    const int tid = threadIdx.x;

    // ---- Stage streamed side (normalize, precompute |vis|^2) ----
    // Scalar float views of the packed arrays: float index j maps to
    // (jp = j/2, half = j&1), which is exactly contiguous layout.
    float* pv0 = (float*)sb0;
    float* pv1 = (float*)sb1;
    float* pv2 = (float*)sb2;
    float* pv3 = (float*)sb3;
    float* pbb = (float*)sbb;
    for (int i = tid; i < N_PART; i += THREADS) {
        const float* r = strp + i * 10;
        float x0 = fmaf(r[0], s0, m0);
        float x1 = fmaf(r[1], s1, m1);
        float v0 = fmaf(r[5], s5, m5);
        float v1 = fmaf(r[6], s6, m6);
        float v2 = fmaf(r[7], s7, m7);
        float v3 = fmaf(r[8], s8, m8);
        pv0[i] = v0;
        pv1[i] = v1;
        pv2[i] = v2;
        pv3[i] = v3;
        pbb[i] = v0 * v0 + v1 * v1 + v2 * v2 + v3 * v3;
        sxy[i] = make_float2(x0, x1);
    }

    // ---- Owned items: a' = -2a, duplicated into both packed halves ----
    ull a0d[ITEMS], a1d[ITEMS], a2d[ITEMS], a3d[ITEMS];
    float aa[ITEMS], ox[ITEMS], oy[ITEMS];
#pragma unroll
    for (int k = 0; k < ITEMS; k++) {
        const int i = tid + k * THREADS;
        const float* r = ownp + i * 10;
        ox[k] = fmaf(r[0], s0, m0);
        oy[k] = fmaf(r[1], s1, m1);
        float a0 = fmaf(r[5], s5, m5);
        float a1 = fmaf(r[6], s6, m6);
        float a2 = fmaf(r[7], s7, m7);
        float a3 = fmaf(r[8], s8, m8);
        aa[k] = a0 * a0 + a1 * a1 + a2 * a2 + a3 * a3;
        a0d[k] = pack_dup(-2.0f * a0);
        a1d[k] = pack_dup(-2.0f * a1);
        a2d[k] = pack_dup(-2.0f * a2);
        a3d[k] = pack_dup(-2.0f * a3);
    }

    __syncthreads();

    float bestd[ITEMS];
    int   bestj[ITEMS];
#pragma unroll
    for (int k = 0; k < ITEMS; k++) { bestd[k] = 3.4e38f; bestj[k] = 0; }

    // ---- Main loop: 2 j's per iteration via packed f32x2 ----
#pragma unroll 4
    for (int jp = 0; jp < NJP; jp++) {
        const ull b0  = sb0[jp];
        const ull b1  = sb1[jp];
        const ull b2  = sb2[jp];
        const ull b3  = sb3[jp];
        const ull acc = sbb[jp];
        const int j0 = jp * 2;
#pragma unroll
        for (int k = 0; k < ITEMS; k++) {
            ull t;
            FMA2(t, a0d[k], b0, acc);
            FMA2(t, a1d[k], b1, t);
            FMA2(t, a2d[k], b2, t);
            FMA2(t, a3d[k], b3, t);
            float lo, hi;
            unpack2(t, lo, hi);
            // strict < keeps the FIRST minimum (matches jnp.argmin tie-break)
            if (lo < bestd[k]) { bestd[k] = lo; bestj[k] = j0; }
            if (hi < bestd[k]) { bestd[k] = hi; bestj[k] = j0 + 1; }
        }
    }

    // ---- Tail: partner XY distance, threshold, accumulate ----
    float partial = 0.0f;
#pragma unroll
    for (int k = 0; k < ITEMS; k++) {
        const float2 p = sxy[bestj[k]];
        const float dx = ox[k] - p.x;
        const float dy = oy[k] - p.y;
        float xd = sqrtf(dx * dx + dy * dy);
        const float min_d = aa[k] + bestd[k];   // true squared latent distance
        if (min_d > 6.0f) xd = 1.0f;            // LATENT_DIST_THRESHOLD
        partial += xd;
    }

    // ---- Block reduce (deterministic) ----
#pragma unroll
    for (int off = 16; off > 0; off >>= 1)
        partial += __shfl_down_sync(0xffffffffu, partial, off);
    if ((tid & 31) == 0) warp_sums[tid >> 5] = partial;
    __syncthreads();
    if (tid == 0) {
        float s = 0.0f;
#pragma unroll
        for (int w = 0; w < THREADS / 32; w++) s += warp_sums[w];
        g_partials[c] = s;
    }
}

__global__ void chamfer_reduce_kernel(float* __restrict__ out)
{
    const int b = threadIdx.x;   // 128 threads
    float s = 0.0f;
#pragma unroll
    for (int t = 0; t < 8; t++) s += g_partials[b * 8 + t];
    out[b] = -s * (1.0f / (1024.0f * 8.0f));
}

extern "C" void kernel_launch(void* const* d_in, const int* in_sizes, int n_in,
                              void* d_out, int out_size)
{
    const float* achieved  = (const float*)d_in[0];
    const float* desired   = (const float*)d_in[1];
    const float* norm_mean = (const float*)d_in[2];
    const float* norm_std  = (const float*)d_in[3];
    float* out = (float*)d_out;

    chamfer_pass_kernel<<<1024, THREADS>>>(achieved, desired, norm_mean, norm_std);
    chamfer_reduce_kernel<<<1, 128>>>(out);
}